// round 8
// baseline (speedup 1.0000x reference)
#include <cuda_runtime.h>
#include <float.h>

#define BN 512
#define DN 256
#define NT 16            // 512 / 32 tiles per dim
#define NBLK 136         // NT*(NT+1)/2 upper-triangular tiles
#define MBLK 128         // mine kernel CTAs (4 warps = 4 anchors each)

typedef unsigned long long u64;

// Scratch (no allocations allowed)
__device__ float g_pd[BN * BN];
__device__ float g_ploss[BN];
__device__ int   g_pcnt[BN];
__device__ unsigned int g_done;    // reset by last CTA each call

__device__ __forceinline__ void fma2(u64& d, u64 a, u64 b) {
    asm("fma.rn.f32x2 %0, %1, %2, %0;" : "+l"(d) : "l"(a), "l"(b));
}
__device__ __forceinline__ float lo32(u64 x) { return __uint_as_float((unsigned)x); }
__device__ __forceinline__ float hi32(u64 x) { return __uint_as_float((unsigned)(x >> 32)); }

// ---------------------------------------------------------------------------
// Kernel A: symmetric pairwise sq-distance GEMM using packed f32x2 FFMA2.
// 136 CTAs x 256 threads, split-K x2 (2 groups x 128 threads).
// Microtile: 2 rows x 4 cols per thread, accumulators packed over row pairs.
// A staged duplicated ({a,a}) so the FFMA2 a-operand is a single LDS.64.
// Norms fused into tile staging. pd = max(sq_i + sq_j - 2 dot, 0), diag 0,
// mirror block written for off-diagonal tiles.
// ---------------------------------------------------------------------------
__global__ void __launch_bounds__(256) pd_fused(const float* __restrict__ emb) {
    __shared__ __align__(16) float2 As2[2][32][32];  // 16KB [g][k][row] = {a,a}
    __shared__ __align__(16) float  Bs[2][32][32];   // 8KB  [g][k][col]
    __shared__ float nAp[2][32], nBp[2][32];
    __shared__ float sqA[32], sqB[32];

    const int tid = threadIdx.x;

    // decode linear block -> (ti, tj), ti <= tj
    int b = blockIdx.x, ti = 0;
    while (b >= NT - ti) { b -= NT - ti; ti++; }
    const int tj = ti + b;
    const int i0 = ti * 32, j0 = tj * 32;

    const int t  = tid & 127;          // thread within k-group
    const int g  = tid >> 7;           // k-group: k in [g*128, g*128+128)
    const int lr = t >> 2;             // staging row 0..31
    const int q  = t & 3;              // k-quartet-pair 0..3 (8 ks each)
    const int ty = t >> 3;             // 0..15 -> rows {2ty, 2ty+1}
    const int tx = t & 7;              // 0..7  -> cols {4tx .. 4tx+3}

    u64 acc[2][2] = {};                // [row u][col-pair p]
    float na = 0.f, nb = 0.f;          // norm partials

    const float* Arow = emb + (i0 + lr) * DN + g * 128 + q * 8;
    const float* Brow = emb + (j0 + lr) * DN + g * 128 + q * 8;

    #pragma unroll
    for (int c0 = 0; c0 < 128; c0 += 32) {
        __syncthreads();
        {
            float4 a0 = *(const float4*)(Arow + c0);
            float4 a1 = *(const float4*)(Arow + c0 + 4);
            float4 b0 = *(const float4*)(Brow + c0);
            float4 b1 = *(const float4*)(Brow + c0 + 4);
            na = fmaf(a0.x, a0.x, fmaf(a0.y, a0.y, fmaf(a0.z, a0.z, fmaf(a0.w, a0.w, na))));
            na = fmaf(a1.x, a1.x, fmaf(a1.y, a1.y, fmaf(a1.z, a1.z, fmaf(a1.w, a1.w, na))));
            nb = fmaf(b0.x, b0.x, fmaf(b0.y, b0.y, fmaf(b0.z, b0.z, fmaf(b0.w, b0.w, nb))));
            nb = fmaf(b1.x, b1.x, fmaf(b1.y, b1.y, fmaf(b1.z, b1.z, fmaf(b1.w, b1.w, nb))));
            const int k0 = q * 8;
            As2[g][k0 + 0][lr] = make_float2(a0.x, a0.x);
            As2[g][k0 + 1][lr] = make_float2(a0.y, a0.y);
            As2[g][k0 + 2][lr] = make_float2(a0.z, a0.z);
            As2[g][k0 + 3][lr] = make_float2(a0.w, a0.w);
            As2[g][k0 + 4][lr] = make_float2(a1.x, a1.x);
            As2[g][k0 + 5][lr] = make_float2(a1.y, a1.y);
            As2[g][k0 + 6][lr] = make_float2(a1.z, a1.z);
            As2[g][k0 + 7][lr] = make_float2(a1.w, a1.w);
            Bs[g][k0 + 0][lr] = b0.x; Bs[g][k0 + 1][lr] = b0.y;
            Bs[g][k0 + 2][lr] = b0.z; Bs[g][k0 + 3][lr] = b0.w;
            Bs[g][k0 + 4][lr] = b1.x; Bs[g][k0 + 5][lr] = b1.y;
            Bs[g][k0 + 6][lr] = b1.z; Bs[g][k0 + 7][lr] = b1.w;
        }
        __syncthreads();
        #pragma unroll
        for (int kk = 0; kk < 32; kk++) {
            const u64* ap = (const u64*)&As2[g][kk][0];   // dup pairs per row
            const u64* bp = (const u64*)&Bs[g][kk][0];    // natural col pairs
            const u64 ad0 = ap[2 * ty];
            const u64 ad1 = ap[2 * ty + 1];
            const u64 bq0 = bp[2 * tx];
            const u64 bq1 = bp[2 * tx + 1];
            fma2(acc[0][0], ad0, bq0);
            fma2(acc[0][1], ad0, bq1);
            fma2(acc[1][0], ad1, bq0);
            fma2(acc[1][1], ad1, bq1);
        }
    }

    // ---- norm combine: 4 threads per row (lanes q=0..3) ----
    na += __shfl_xor_sync(0xffffffffu, na, 1);
    na += __shfl_xor_sync(0xffffffffu, na, 2);
    nb += __shfl_xor_sync(0xffffffffu, nb, 1);
    nb += __shfl_xor_sync(0xffffffffu, nb, 2);
    if (q == 0) { nAp[g][lr] = na; nBp[g][lr] = nb; }
    __syncthreads();

    // group 1 parks partials in As2 scratch (4 float2 per thread)
    if (g == 1) {
        float2* scr = (float2*)&As2[0][0][0];
        scr[t * 4 + 0] = make_float2(lo32(acc[0][0]), hi32(acc[0][0]));
        scr[t * 4 + 1] = make_float2(lo32(acc[0][1]), hi32(acc[0][1]));
        scr[t * 4 + 2] = make_float2(lo32(acc[1][0]), hi32(acc[1][0]));
        scr[t * 4 + 3] = make_float2(lo32(acc[1][1]), hi32(acc[1][1]));
    }
    if (g == 0) {
        if (t < 32) sqA[t] = nAp[0][t] + nAp[1][t];
        else if (t < 64) sqB[t - 32] = nBp[0][t - 32] + nBp[1][t - 32];
    }
    __syncthreads();

    if (g == 0) {
        const float2* scr = (const float2*)&As2[0][0][0];
        float d[2][4];
        #pragma unroll
        for (int u = 0; u < 2; u++) {
            const int gi = i0 + 2 * ty + u;
            const float sqi = sqA[2 * ty + u];
            #pragma unroll
            for (int p = 0; p < 2; p++) {
                const float2 pr = scr[t * 4 + u * 2 + p];
                const float dot0 = lo32(acc[u][p]) + pr.x;
                const float dot1 = hi32(acc[u][p]) + pr.y;
                const int gj0 = j0 + 4 * tx + 2 * p;
                float v0 = fmaxf(sqi + sqB[4 * tx + 2 * p] - 2.f * dot0, 0.f);
                float v1 = fmaxf(sqi + sqB[4 * tx + 2 * p + 1] - 2.f * dot1, 0.f);
                if (gi == gj0) v0 = 0.f;
                if (gi == gj0 + 1) v1 = 0.f;
                d[u][2 * p] = v0;
                d[u][2 * p + 1] = v1;
            }
            *(float4*)(g_pd + gi * BN + j0 + 4 * tx) =
                make_float4(d[u][0], d[u][1], d[u][2], d[u][3]);
        }
        if (ti != tj) {
            #pragma unroll
            for (int v = 0; v < 4; v++) {
                const int gj = j0 + 4 * tx + v;
                *(float2*)(g_pd + gj * BN + i0 + 2 * ty) =
                    make_float2(d[0][v], d[1][v]);
            }
        }
    }
}

// ---------------------------------------------------------------------------
// Kernel B: warp-per-anchor semi-hard mining + fused final reduction.
// 128 CTAs x 128 threads; warp w of CTA cb owns anchor j = cb*4 + w.
// ---------------------------------------------------------------------------
__global__ void __launch_bounds__(128) mine_final(const int* __restrict__ labels,
                                                  float* __restrict__ out) {
    const int tid = threadIdx.x;
    const int lane = tid & 31, w = tid >> 5;
    const unsigned FULL = 0xffffffffu;

    __shared__ int   s_lab[BN];
    __shared__ float s_row[4][BN];
    __shared__ int s_last;

    #pragma unroll
    for (int k = tid; k < BN; k += 128) s_lab[k] = labels[k];
    __syncthreads();

    const int j = blockIdx.x * 4 + w;          // anchor (0..511)
    const int lj = s_lab[j];
    const float* rowp = g_pd + j * BN;

    float v[16];
    unsigned nmask = 0, pmask = 0;
    #pragma unroll
    for (int c = 0; c < 16; c++) {
        const int k = c * 32 + lane;
        v[c] = rowp[k];
        s_row[w][k] = v[c];
        const bool same = (s_lab[k] == lj);
        if (!same) nmask |= (1u << c);
        if (same && k != j) pmask |= (1u << c);
    }

    float mx = -FLT_MAX, mn = FLT_MAX;
    #pragma unroll
    for (int c = 0; c < 16; c++) {
        if ((nmask >> c) & 1) mx = fmaxf(mx, v[c]);
        mn = fminf(mn, v[c]);
    }
    #pragma unroll
    for (int o = 16; o; o >>= 1) {
        mx = fmaxf(mx, __shfl_xor_sync(FULL, mx, o));
        mn = fminf(mn, __shfl_xor_sync(FULL, mn, o));
    }
    const float ninside = (mx > -FLT_MAX) ? mx : mn;

    float wsum = 0.f;
    int cnt = 0;
    int pend = -1;
    #pragma unroll 1
    for (int c = 0; c < 16; c++) {
        unsigned pm = __ballot_sync(FULL, (pmask >> c) & 1);
        while (pm) {
            const int bb = __ffs(pm) - 1;
            pm &= pm - 1;
            const int i = c * 32 + bb;
            cnt++;
            if (pend < 0) { pend = i; continue; }
            const float t1 = s_row[w][pend];
            const float t2 = s_row[w][i];
            float m1 = FLT_MAX, m2 = FLT_MAX;
            #pragma unroll
            for (int cc = 0; cc < 16; cc++) {
                if ((nmask >> cc) & 1) {
                    const float x = v[cc];
                    if (x > t1) m1 = fminf(m1, x);
                    if (x > t2) m2 = fminf(m2, x);
                }
            }
            #pragma unroll
            for (int o = 16; o; o >>= 1) {
                m1 = fminf(m1, __shfl_xor_sync(FULL, m1, o));
                m2 = fminf(m2, __shfl_xor_sync(FULL, m2, o));
            }
            const float semi1 = (m1 < FLT_MAX) ? m1 : ninside;
            const float semi2 = (m2 < FLT_MAX) ? m2 : ninside;
            wsum += fmaxf(1.0f + t1 - semi1, 0.f);
            wsum += fmaxf(1.0f + t2 - semi2, 0.f);
            pend = -1;
        }
    }
    if (pend >= 0) {
        const float t1 = s_row[w][pend];
        float m1 = FLT_MAX;
        #pragma unroll
        for (int cc = 0; cc < 16; cc++) {
            if ((nmask >> cc) & 1) {
                const float x = v[cc];
                if (x > t1) m1 = fminf(m1, x);
            }
        }
        #pragma unroll
        for (int o = 16; o; o >>= 1)
            m1 = fminf(m1, __shfl_xor_sync(FULL, m1, o));
        const float semi1 = (m1 < FLT_MAX) ? m1 : ninside;
        wsum += fmaxf(1.0f + t1 - semi1, 0.f);
    }

    if (lane == 0) {
        g_ploss[j] = wsum;
        g_pcnt[j]  = cnt;
    }
    __syncthreads();
    if (tid == 0) {
        __threadfence();
        const unsigned int vd = atomicAdd(&g_done, 1u);
        s_last = (vd == (unsigned)(gridDim.x - 1)) ? 1 : 0;
    }
    __syncthreads();

    if (s_last) {
        __threadfence();  // acquire
        float s = 0.f, c = 0.f;
        #pragma unroll
        for (int r = 0; r < 4; r++) {
            s += g_ploss[tid + r * 128];
            c += (float)g_pcnt[tid + r * 128];
        }
        #pragma unroll
        for (int o = 16; o; o >>= 1) {
            s += __shfl_xor_sync(FULL, s, o);
            c += __shfl_xor_sync(FULL, c, o);
        }
        __shared__ float ss[4], cc2[4];
        if (lane == 0) { ss[w] = s; cc2[w] = c; }
        __syncthreads();
        if (tid == 0) {
            float ts = 0.f, tc = 0.f;
            #pragma unroll
            for (int i = 0; i < 4; i++) { ts += ss[i]; tc += cc2[i]; }
            out[0] = ts / tc;
            g_done = 0;   // reset for next graph replay
        }
    }
}

// ---------------------------------------------------------------------------
extern "C" void kernel_launch(void* const* d_in, const int* in_sizes, int n_in,
                              void* d_out, int out_size) {
    const float* emb = (const float*)d_in[0];
    const int* labels = (const int*)d_in[1];
    float* out = (float*)d_out;

    pd_fused<<<NBLK, 256>>>(emb);
    mine_final<<<MBLK, 128>>>(labels, out);
}

// round 9
// speedup vs baseline: 1.1050x; 1.1050x over previous
#include <cuda_runtime.h>
#include <float.h>

#define BN 512
#define DN 256
#define NT 16             // 512 / 32 tiles per dim
#define NBLK 136          // NT*(NT+1)/2 upper-triangular producer tiles
#define MINE_CTAS 64      // consumer CTAs: 8 warps = 8 anchors each
#define TOTAL_CTAS (NBLK + MINE_CTAS)

// Scratch (no allocations allowed)
__device__ float g_pd[BN * BN];
__device__ float g_ploss[BN];
__device__ int   g_pcnt[BN];
__device__ unsigned int g_rowcnt[NT];  // tiles completed per 32-row group
__device__ unsigned int g_done;        // consumer-done counter

union SmemU {
    struct {
        float As[4][32][32];   // reused as partial-sum scratch after main loop
        float Bs[4][32][32];
        float nA[4][32], nB[4][32];
        float sqA[32], sqB[32];
    } pd;
    struct {
        int   lab[BN];
        float row[8][BN];
    } mine;
};

// ---------------------------------------------------------------------------
// Single launch, 200 CTAs x 256 threads:
//  CTAs [0,136):  producer — symmetric pd GEMM tile (split-K x4, fused norms),
//                 then release per-row-group counters.
//  CTAs [136,200): consumer — spin on own row-group counter, then
//                 warp-per-anchor semi-hard mining (8 anchors/CTA);
//                 last-done consumer does the final reduction + counter reset.
// All 200 CTAs are wave-1 co-resident (launch_bounds(256,2)), producers never
// wait on consumers -> progress guaranteed.
// ---------------------------------------------------------------------------
__global__ void __launch_bounds__(256, 2)
triplet_overlap(const float* __restrict__ emb,
                const int* __restrict__ labels,
                float* __restrict__ out) {
    __shared__ SmemU sm;
    const int tid = threadIdx.x;
    const int lane = tid & 31, widx = tid >> 5;
    const unsigned FULL = 0xffffffffu;

    if (blockIdx.x < NBLK) {
        // ====================== PRODUCER: pd GEMM tile ======================
        int b = blockIdx.x, ti = 0;
        while (b >= NT - ti) { b -= NT - ti; ti++; }
        const int tj = ti + b;
        const int i0 = ti * 32, j0 = tj * 32;

        const int t    = tid & 63;
        const int g    = tid >> 6;             // 0..3, k in [g*64, g*64+64)
        const int lr   = t >> 1;               // load row 0..31
        const int half = t & 1;                // k-half within 32-chunk
        const int ty   = t >> 3;               // 0..7 -> 4 i-rows
        const int tx   = t & 7;                // 0..7 -> 4 j-cols

        float acc[4][4] = {};
        float na = 0.f, nb = 0.f;              // norm partials

        {
            const float* Arow = emb + (i0 + lr) * DN + g * 64;
            const float* Brow = emb + (j0 + lr) * DN + g * 64;

            #pragma unroll
            for (int c0 = 0; c0 < 64; c0 += 32) {
                __syncthreads();
                #pragma unroll
                for (int e = 0; e < 4; e++) {
                    const int ko = half * 16 + e * 4;
                    float4 a4 = *(const float4*)(Arow + c0 + ko);
                    float4 b4 = *(const float4*)(Brow + c0 + ko);
                    na = fmaf(a4.x, a4.x, fmaf(a4.y, a4.y, fmaf(a4.z, a4.z, fmaf(a4.w, a4.w, na))));
                    nb = fmaf(b4.x, b4.x, fmaf(b4.y, b4.y, fmaf(b4.z, b4.z, fmaf(b4.w, b4.w, nb))));
                    sm.pd.As[g][ko + 0][lr] = a4.x; sm.pd.As[g][ko + 1][lr] = a4.y;
                    sm.pd.As[g][ko + 2][lr] = a4.z; sm.pd.As[g][ko + 3][lr] = a4.w;
                    sm.pd.Bs[g][ko + 0][lr] = b4.x; sm.pd.Bs[g][ko + 1][lr] = b4.y;
                    sm.pd.Bs[g][ko + 2][lr] = b4.z; sm.pd.Bs[g][ko + 3][lr] = b4.w;
                }
                __syncthreads();
                #pragma unroll
                for (int kk = 0; kk < 32; kk++) {
                    float4 av = *(const float4*)&sm.pd.As[g][kk][ty << 2];
                    float4 bv = *(const float4*)&sm.pd.Bs[g][kk][tx << 2];
                    float ar[4] = {av.x, av.y, av.z, av.w};
                    float br[4] = {bv.x, bv.y, bv.z, bv.w};
                    #pragma unroll
                    for (int u = 0; u < 4; u++)
                        #pragma unroll
                        for (int v = 0; v < 4; v++)
                            acc[u][v] = fmaf(ar[u], br[v], acc[u][v]);
                }
            }
        }

        // norm combine: lanes (2m, 2m+1) share row lr
        na += __shfl_xor_sync(FULL, na, 1);
        nb += __shfl_xor_sync(FULL, nb, 1);
        if (!half) { sm.pd.nA[g][lr] = na; sm.pd.nB[g][lr] = nb; }
        __syncthreads();
        if (g == 0) {
            if (t < 32) sm.pd.sqA[t] = (sm.pd.nA[0][t] + sm.pd.nA[1][t]) + (sm.pd.nA[2][t] + sm.pd.nA[3][t]);
            else        sm.pd.sqB[t - 32] = (sm.pd.nB[0][t - 32] + sm.pd.nB[1][t - 32]) + (sm.pd.nB[2][t - 32] + sm.pd.nB[3][t - 32]);
        }
        if (g > 0) {
            float* dst = &sm.pd.As[0][0][0] + ((g - 1) * 64 + t) * 16;
            #pragma unroll
            for (int u = 0; u < 4; u++)
                #pragma unroll
                for (int v = 0; v < 4; v++) dst[u * 4 + v] = acc[u][v];
        }
        __syncthreads();

        if (g == 0) {
            const float* p1 = &sm.pd.As[0][0][0] + (0 * 64 + t) * 16;
            const float* p2 = &sm.pd.As[0][0][0] + (1 * 64 + t) * 16;
            const float* p3 = &sm.pd.As[0][0][0] + (2 * 64 + t) * 16;
            float d[4][4];
            #pragma unroll
            for (int u = 0; u < 4; u++) {
                const int gi = i0 + (ty << 2) + u;
                const float sqi = sm.pd.sqA[(ty << 2) + u];
                #pragma unroll
                for (int v = 0; v < 4; v++) {
                    const int gj = j0 + (tx << 2) + v;
                    const int e = u * 4 + v;
                    const float dot = (acc[u][v] + p1[e]) + (p2[e] + p3[e]);
                    float val = fmaxf(sqi + sm.pd.sqB[(tx << 2) + v] - 2.f * dot, 0.f);
                    if (gi == gj) val = 0.f;
                    d[u][v] = val;
                }
                *(float4*)(g_pd + gi * BN + j0 + (tx << 2)) =
                    make_float4(d[u][0], d[u][1], d[u][2], d[u][3]);
            }
            if (ti != tj) {
                #pragma unroll
                for (int v = 0; v < 4; v++) {
                    const int gj = j0 + (tx << 2) + v;
                    *(float2*)(g_pd + gj * BN + i0 + (ty << 2)) =
                        make_float2(d[0][v], d[1][v]);
                    *(float2*)(g_pd + gj * BN + i0 + (ty << 2) + 2) =
                        make_float2(d[2][v], d[3][v]);
                }
            }
        }

        // release: bump row-group counters (16 tiles complete a group)
        __syncthreads();
        if (tid == 0) {
            __threadfence();
            atomicAdd(&g_rowcnt[ti], 1u);
            if (tj != ti) atomicAdd(&g_rowcnt[tj], 1u);
        }
        return;
    }

    // ========================= CONSUMER: mining =============================
    const int cb = blockIdx.x - NBLK;          // 0..63
    __shared__ int s_last;

    // load labels while waiting for our row group
    for (int k = tid; k < BN; k += 256) sm.mine.lab[k] = labels[k];
    __syncthreads();

    const int grp = cb >> 2;                   // 32-row group of our 8 anchors
    if (tid == 0) {
        while (*(volatile unsigned int*)&g_rowcnt[grp] < 16u) { __nanosleep(64); }
    }
    __syncthreads();
    __threadfence();                           // acquire: g_pd rows visible

    const int j = cb * 8 + widx;               // anchor (0..511)
    const int lj = sm.mine.lab[j];
    const float* rowp = g_pd + j * BN;

    float v[16];
    unsigned nmask = 0, pmask = 0;
    #pragma unroll
    for (int c = 0; c < 16; c++) {
        const int k = c * 32 + lane;
        v[c] = rowp[k];
        sm.mine.row[widx][k] = v[c];
        const bool same = (sm.mine.lab[k] == lj);
        if (!same) nmask |= (1u << c);
        if (same && k != j) pmask |= (1u << c);
    }

    float mx = -FLT_MAX, mn = FLT_MAX;
    #pragma unroll
    for (int c = 0; c < 16; c++) {
        if ((nmask >> c) & 1) mx = fmaxf(mx, v[c]);
        mn = fminf(mn, v[c]);
    }
    #pragma unroll
    for (int o = 16; o; o >>= 1) {
        mx = fmaxf(mx, __shfl_xor_sync(FULL, mx, o));
        mn = fminf(mn, __shfl_xor_sync(FULL, mn, o));
    }
    const float ninside = (mx > -FLT_MAX) ? mx : mn;

    float wsum = 0.f;
    int cnt = 0;
    int pend = -1;
    #pragma unroll 1
    for (int c = 0; c < 16; c++) {
        unsigned pm = __ballot_sync(FULL, (pmask >> c) & 1);
        while (pm) {
            const int bb = __ffs(pm) - 1;
            pm &= pm - 1;
            const int i = c * 32 + bb;
            cnt++;
            if (pend < 0) { pend = i; continue; }
            const float t1 = sm.mine.row[widx][pend];
            const float t2 = sm.mine.row[widx][i];
            float m1 = FLT_MAX, m2 = FLT_MAX;
            #pragma unroll
            for (int cc = 0; cc < 16; cc++) {
                if ((nmask >> cc) & 1) {
                    const float x = v[cc];
                    if (x > t1) m1 = fminf(m1, x);
                    if (x > t2) m2 = fminf(m2, x);
                }
            }
            #pragma unroll
            for (int o = 16; o; o >>= 1) {
                m1 = fminf(m1, __shfl_xor_sync(FULL, m1, o));
                m2 = fminf(m2, __shfl_xor_sync(FULL, m2, o));
            }
            const float semi1 = (m1 < FLT_MAX) ? m1 : ninside;
            const float semi2 = (m2 < FLT_MAX) ? m2 : ninside;
            wsum += fmaxf(1.0f + t1 - semi1, 0.f);
            wsum += fmaxf(1.0f + t2 - semi2, 0.f);
            pend = -1;
        }
    }
    if (pend >= 0) {
        const float t1 = sm.mine.row[widx][pend];
        float m1 = FLT_MAX;
        #pragma unroll
        for (int cc = 0; cc < 16; cc++) {
            if ((nmask >> cc) & 1) {
                const float x = v[cc];
                if (x > t1) m1 = fminf(m1, x);
            }
        }
        #pragma unroll
        for (int o = 16; o; o >>= 1)
            m1 = fminf(m1, __shfl_xor_sync(FULL, m1, o));
        const float semi1 = (m1 < FLT_MAX) ? m1 : ninside;
        wsum += fmaxf(1.0f + t1 - semi1, 0.f);
    }

    if (lane == 0) {
        g_ploss[j] = wsum;
        g_pcnt[j]  = cnt;
    }
    __syncthreads();
    if (tid == 0) {
        __threadfence();
        const unsigned int vd = atomicAdd(&g_done, 1u);
        s_last = (vd == (unsigned)(MINE_CTAS - 1)) ? 1 : 0;
    }
    __syncthreads();

    // last consumer: deterministic final reduction + counter reset
    if (s_last) {
        __threadfence();  // acquire
        float s = g_ploss[tid] + g_ploss[tid + 256];
        float c = (float)(g_pcnt[tid] + g_pcnt[tid + 256]);
        #pragma unroll
        for (int o = 16; o; o >>= 1) {
            s += __shfl_xor_sync(FULL, s, o);
            c += __shfl_xor_sync(FULL, c, o);
        }
        __shared__ float ss[8], cc2[8];
        if (lane == 0) { ss[widx] = s; cc2[widx] = c; }
        __syncthreads();
        if (tid < NT) g_rowcnt[tid] = 0;       // reset for next graph replay
        if (tid == 0) {
            float ts = 0.f, tc = 0.f;
            #pragma unroll
            for (int i = 0; i < 8; i++) { ts += ss[i]; tc += cc2[i]; }
            out[0] = ts / tc;
            g_done = 0;
        }
    }
}

// ---------------------------------------------------------------------------
extern "C" void kernel_launch(void* const* d_in, const int* in_sizes, int n_in,
                              void* d_out, int out_size) {
    const float* emb = (const float*)d_in[0];
    const int* labels = (const int*)d_in[1];
    float* out = (float*)d_out;

    triplet_overlap<<<TOTAL_CTAS, 256>>>(emb, labels, out);
}